// round 2
// baseline (speedup 1.0000x reference)
#include <cuda_runtime.h>
#include <cuda_bf16.h>

// GCN: h1 = relu(GCNConv(x, W1, b1)); h2 = relu(GCNConv(h1, W2, b2));
// out = mean_pool_per_graph(h2) @ Wlin + blin
//
// Factorization: GCNConv(x)_i = dinv[i] * ( sum_{e:dst=i} hs[src_e] + hs[i] ) + b
// where hs = (x @ W) * dinv[row],  dinv = rsqrt(deg+1).
//
// NOTE: all scratch is __device__ globals referenced ONLY from device code
// (a __device__ symbol passed as a host-side kernel arg is NOT a valid
// device pointer — that was the round-1 crash).

#define NN 50000
#define NE 800000
#define HID 64

// ---- scratch (static device globals; no allocation allowed) ----
__device__ __align__(16) float g_deg[NN];
__device__ __align__(16) float g_dinv[NN];
__device__ __align__(16) float g_hs[NN * HID];   // hs for current layer
__device__ __align__(16) float g_agg[NN * HID];  // scatter accumulator
__device__ __align__(16) float g_out1[NN * HID]; // layer-1 activation
__device__ __align__(16) float g_gbuf[128];      // [0:64) graph sums, [64:128) counts

// ---------------------------------------------------------------------------
// 1) deg init
__global__ void k_deg_init(int n) {
    int i = blockIdx.x * blockDim.x + threadIdx.x;
    if (i < n) g_deg[i] = 1.0f;
}

// 2) deg count: deg[dst] += 1 per edge
__global__ void k_deg_count(const int* __restrict__ dst, int ne) {
    int e = blockIdx.x * blockDim.x + threadIdx.x;
    if (e < ne) atomicAdd(&g_deg[dst[e]], 1.0f);
}

// 3) dinv = rsqrt(deg); zero agg
__global__ void k_dinv_zero(int n) {
    int i = blockIdx.x * blockDim.x + threadIdx.x;
    if (i < n) g_dinv[i] = rsqrtf(g_deg[i]);
    if (i < n * (HID / 4)) {
        reinterpret_cast<float4*>(g_agg)[i] = make_float4(0.f, 0.f, 0.f, 0.f);
    }
}

// zero agg (+ graph buffers) for layer 2
__global__ void k_zero2(int n) {
    int i = blockIdx.x * blockDim.x + threadIdx.x;
    if (i < 128) g_gbuf[i] = 0.0f;
    if (i < n * (HID / 4)) {
        reinterpret_cast<float4*>(g_agg)[i] = make_float4(0.f, 0.f, 0.f, 0.f);
    }
}

// ---------------------------------------------------------------------------
// GEMM: g_hs[r, 0:64] = (X[r, 0:K] @ W[K, 64]) * dinv[r]
// X == nullptr -> read g_out1 (layer 2). Output always g_hs (device symbol).
// Block: 256 threads, 64-row tile, K processed in 64-chunks.
template <int K>
__global__ __launch_bounds__(256) void k_gemm(
    const float* __restrict__ Xin, const float* __restrict__ W, int nrows)
{
    const float* __restrict__ X = Xin ? Xin : g_out1;

    __shared__ float Xs[64][68];   // padded stride: conflict-free column reads
    __shared__ float Ws[64][64];

    const int tid = threadIdx.x;
    const int row0 = blockIdx.x * 64;
    const int tx = tid & 15;   // col group: cols tx*4 .. tx*4+3
    const int ty = tid >> 4;   // row group: rows ty*4 .. ty*4+3

    float acc[4][4] = {};

    for (int k0 = 0; k0 < K; k0 += 64) {
        // load W chunk [64 x 64] via float4
        for (int i = tid; i < 64 * 16; i += 256) {
            reinterpret_cast<float4*>(&Ws[0][0])[i] =
                reinterpret_cast<const float4*>(W + (size_t)k0 * 64)[i];
        }
        // load X chunk [64 rows x 64 cols]
        for (int i = tid; i < 64 * 16; i += 256) {
            int r = i >> 4;
            int c = (i & 15) * 4;
            int gr = row0 + r;
            float4 v = make_float4(0.f, 0.f, 0.f, 0.f);
            if (gr < nrows)
                v = *reinterpret_cast<const float4*>(X + (size_t)gr * K + k0 + c);
            Xs[r][c + 0] = v.x; Xs[r][c + 1] = v.y;
            Xs[r][c + 2] = v.z; Xs[r][c + 3] = v.w;
        }
        __syncthreads();

        #pragma unroll 8
        for (int kk = 0; kk < 64; kk++) {
            float4 wv = *reinterpret_cast<const float4*>(&Ws[kk][tx * 4]);
            float x0 = Xs[ty * 4 + 0][kk];
            float x1 = Xs[ty * 4 + 1][kk];
            float x2 = Xs[ty * 4 + 2][kk];
            float x3 = Xs[ty * 4 + 3][kk];
            acc[0][0] += x0 * wv.x; acc[0][1] += x0 * wv.y;
            acc[0][2] += x0 * wv.z; acc[0][3] += x0 * wv.w;
            acc[1][0] += x1 * wv.x; acc[1][1] += x1 * wv.y;
            acc[1][2] += x1 * wv.z; acc[1][3] += x1 * wv.w;
            acc[2][0] += x2 * wv.x; acc[2][1] += x2 * wv.y;
            acc[2][2] += x2 * wv.z; acc[2][3] += x2 * wv.w;
            acc[3][0] += x3 * wv.x; acc[3][1] += x3 * wv.y;
            acc[3][2] += x3 * wv.z; acc[3][3] += x3 * wv.w;
        }
        __syncthreads();
    }

    #pragma unroll
    for (int r = 0; r < 4; r++) {
        int gr = row0 + ty * 4 + r;
        if (gr < nrows) {
            float s = g_dinv[gr];
            float4 o = make_float4(acc[r][0] * s, acc[r][1] * s,
                                   acc[r][2] * s, acc[r][3] * s);
            reinterpret_cast<float4*>(g_hs + (size_t)gr * 64)[tx] = o;
        }
    }
}

// ---------------------------------------------------------------------------
// Edge scatter: agg[dst] += hs[src]   (64 floats = 16 lanes x float4 per edge)
__global__ __launch_bounds__(256) void k_scatter(
    const int* __restrict__ src, const int* __restrict__ dst, int ne)
{
    int idx = blockIdx.x * blockDim.x + threadIdx.x;
    int e = idx >> 4;
    if (e >= ne) return;
    int q = idx & 15;
    int s = __ldg(src + e);
    int d = __ldg(dst + e);
    float4 v = reinterpret_cast<const float4*>(g_hs)[(size_t)s * 16 + q];
    float* p = g_agg + ((size_t)d * 64 + q * 4);
    asm volatile("red.global.add.v4.f32 [%0], {%1,%2,%3,%4};"
                 :: "l"(p), "f"(v.x), "f"(v.y), "f"(v.z), "f"(v.w)
                 : "memory");
}

// ---------------------------------------------------------------------------
// Post layer 1: out1 = relu(dinv[i]*(agg[i]+hs[i]) + b1)
__global__ void k_post1(const float* __restrict__ b, int n) {
    int idx = blockIdx.x * blockDim.x + threadIdx.x;  // over n*16 float4s
    if (idx >= n * 16) return;
    int row = idx >> 4;
    int q = idx & 15;
    float s = g_dinv[row];
    float4 a = reinterpret_cast<const float4*>(g_agg)[idx];
    float4 h = reinterpret_cast<const float4*>(g_hs)[idx];
    float4 bb = reinterpret_cast<const float4*>(b)[q];
    float4 o;
    o.x = fmaxf(0.f, s * (a.x + h.x) + bb.x);
    o.y = fmaxf(0.f, s * (a.y + h.y) + bb.y);
    o.z = fmaxf(0.f, s * (a.z + h.z) + bb.z);
    o.w = fmaxf(0.f, s * (a.w + h.w) + bb.w);
    reinterpret_cast<float4*>(g_out1)[idx] = o;
}

// ---------------------------------------------------------------------------
// Post layer 2 fused with pooling head:
// per node: v = relu(dinv*(agg+hs)+b2);  dot(v, Wlin) -> atomicAdd to graph sum
__global__ __launch_bounds__(256) void k_post2_reduce(
    const float* __restrict__ b2, const float* __restrict__ Wlin,
    const int* __restrict__ batch, int n)
{
    int node = (blockIdx.x * blockDim.x + threadIdx.x) >> 5;
    int lane = threadIdx.x & 31;
    if (node >= n) return;
    float s = g_dinv[node];
    float acc = 0.f;
    #pragma unroll
    for (int j0 = 0; j0 < 64; j0 += 32) {
        int j = j0 + lane;
        float v = fmaxf(0.f,
            s * (g_agg[(size_t)node * 64 + j] + g_hs[(size_t)node * 64 + j])
            + __ldg(b2 + j));
        acc += v * __ldg(Wlin + j);
    }
    #pragma unroll
    for (int o = 16; o; o >>= 1) acc += __shfl_xor_sync(0xFFFFFFFFu, acc, o);
    if (lane == 0) {
        int g = __ldg(batch + node);
        atomicAdd(&g_gbuf[g], acc);
        atomicAdd(&g_gbuf[64 + g], 1.0f);
    }
}

// ---------------------------------------------------------------------------
__global__ void k_finalize(const float* __restrict__ blin, float* __restrict__ out) {
    int g = threadIdx.x;
    if (g < 64) out[g] = g_gbuf[g] / fmaxf(g_gbuf[64 + g], 1.0f) + blin[0];
}

// ---------------------------------------------------------------------------
extern "C" void kernel_launch(void* const* d_in, const int* in_sizes, int n_in,
                              void* d_out, int out_size)
{
    const float* x     = (const float*)d_in[0];
    const int*   eidx  = (const int*)d_in[1];
    const int*   batch = (const int*)d_in[2];
    const float* W1    = (const float*)d_in[3];
    const float* b1    = (const float*)d_in[4];
    const float* W2    = (const float*)d_in[5];
    const float* b2    = (const float*)d_in[6];
    const float* Wlin  = (const float*)d_in[7];
    const float* blin  = (const float*)d_in[8];
    float* out = (float*)d_out;

    const int N = in_sizes[0] / 128;   // 50000
    const int E = in_sizes[1] / 2;     // 800000
    const int* src = eidx;
    const int* dst = eidx + E;

    const int T = 256;

    // degree + norm
    k_deg_init<<<(N + T - 1) / T, T>>>(N);
    k_deg_count<<<(E + T - 1) / T, T>>>(dst, E);
    k_dinv_zero<<<(N * 16 + T - 1) / T, T>>>(N);

    // layer 1
    k_gemm<128><<<(N + 63) / 64, 256>>>(x, W1, N);
    {
        long long w = (long long)E * 16;
        k_scatter<<<(int)((w + T - 1) / T), T>>>(src, dst, E);
    }
    k_post1<<<(N * 16 + T - 1) / T, T>>>(b1, N);

    // layer 2
    k_zero2<<<(N * 16 + T - 1) / T, T>>>(N);
    k_gemm<64><<<(N + 63) / 64, 256>>>(nullptr, W2, N);
    {
        long long w = (long long)E * 16;
        k_scatter<<<(int)((w + T - 1) / T), T>>>(src, dst, E);
    }

    // fused post + pooling head
    k_post2_reduce<<<(N * 32 + T - 1) / T, T>>>(b2, Wlin, batch, N);
    k_finalize<<<1, 64>>>(blin, out);
}